// round 5
// baseline (speedup 1.0000x reference)
#include <cuda_runtime.h>
#include <math_constants.h>

#define NORB   1024
#define NTIMES 1024
#define NFZ    24
#define NKEZ   6
#define NTINT  64
#define NALPHA 512

#define HTINT    16                     // tints per CTA (quarter)
#define NTHREADS 512
#define NWARPS   16
#define EPG      4                      // epochs per CTA group

// smem layout (floats): slab2[512*16] float2 = 16384f | sf[1024] float2 = 2048f | ssv[512] uint = 512f
#define SF_OFF   16384
#define SS_OFF   (SF_OFF + 2048)
#define SMEM_BYTES ((SS_OFF + 512) * 4)   // 75776 B -> 3 CTAs/SM

// device scratch
__device__ float2         g_f[NTIMES * NORB];   // (dalpha, dMag_masked)
__device__ unsigned short g_s[NTIMES * NORB];   // s index
__device__ unsigned short g_order[NTIMES];      // epochs sorted by fZ bin

// ---------------- pre-kernel 1: per-(epoch,orbit) stage, transposed ---------
__global__ __launch_bounds__(1024)
void stage_kernel(const float* __restrict__ alpha,
                  const float* __restrict__ dMag,
                  const float* __restrict__ alphas)
{
    __shared__ float2         tf[32][33];
    __shared__ unsigned short ts[32][33];
    const int tx = threadIdx.x, ty = threadIdx.y;
    const int t = blockIdx.x * 32 + tx;
    const int o = blockIdx.y * 32 + ty;

    const float a_lo   = alphas[0];
    const float a_hi   = alphas[NALPHA - 1];
    const float la0    = log10f(a_lo);
    const float inv_la = 1.0f / (log10f(alphas[1]) - la0);

    float av = alpha[(size_t)o * NTIMES + t];
    float dm = dMag [(size_t)o * NTIMES + t];
    bool  m  = (av >= a_lo) && (av <= a_hi);
    float aind = (log10f(av) - la0) * inv_la;
    int a0 = (int)aind;                            // trunc == astype(int32)
    a0 = max(0, min(a0, NALPHA - 1));
    float dal = aind - (float)a0;                  // dalpha vs clipped a0 (reference quirk)
    int s = min(a0, NALPHA - 2);                   // dynamic_slice clamp
    if (!m) dm = CUDART_INF_F;                     // geom_mask folded

    tf[ty][tx] = make_float2(dal, dm);
    ts[ty][tx] = (unsigned short)s;
    __syncthreads();

    const int tw = blockIdx.x * 32 + ty;
    const int ow = blockIdx.y * 32 + tx;
    g_f[(size_t)tw * NORB + ow] = tf[tx][ty];
    g_s[(size_t)tw * NORB + ow] = ts[tx][ty];
}

// ---------------- pre-kernel 2: sort epochs by fZ bin (1 block) -------------
__global__ __launch_bounds__(NTIMES)
void bin_kernel(const float* __restrict__ fZ_vals,
                const float* __restrict__ fZs)
{
    __shared__ int hist[NFZ];
    __shared__ int offs[NFZ];
    const int t = threadIdx.x;
    if (t < NFZ) hist[t] = 0;
    __syncthreads();

    const float lf0    = log10f(fZs[0]);
    const float inv_lf = 1.0f / (log10f(fZs[1]) - lf0);
    float find = (log10f(fZ_vals[t]) - lf0) * inv_lf;
    int f0 = (int)floorf(find) + 1;
    f0 = max(0, min(f0, NFZ - 2));
    atomicAdd(&hist[f0], 1);
    __syncthreads();

    if (t == 0) {
        int acc = 0;
        #pragma unroll
        for (int i = 0; i < NFZ; ++i) { offs[i] = acc; acc += hist[i]; }
    }
    __syncthreads();
    int pos = atomicAdd(&offs[f0], 1);
    g_order[pos] = (unsigned short)t;
}

// ---------------- main kernel: CTA = (epoch-group, tint-quarter) ------------
__global__ __launch_bounds__(NTHREADS, 3)
void pdet_kernel(const float* __restrict__ fZ_vals,
                 const float* __restrict__ kEZ_val,
                 const float* __restrict__ grid,
                 const float* __restrict__ fZs,
                 const float* __restrict__ kEZs,
                 float* __restrict__ out)
{
    extern __shared__ float sm[];
    float2*       slab2 = (float2*)sm;              // [512][16] (g0, g1-g0)
    float2*       sf    = (float2*)(sm + SF_OFF);   // [1024] (dal, dm)
    unsigned int* ssv   = (unsigned int*)(sm + SS_OFF); // [512] packed 2x u16

    const int grp = blockIdx.x;
    const int h   = blockIdx.y;                     // tint quarter
    const int tid = threadIdx.x;
    const int w     = tid >> 5;
    const int lane  = tid & 31;
    const int tint  = lane & 15;
    const int ohalf = lane >> 4;

    const float kv = kEZ_val[0];
    int kez = -1;
    #pragma unroll
    for (int i = 0; i < NKEZ; ++i) kez += (kEZs[i] <= kv) ? 1 : 0;
    kez = max(0, min(kez, NKEZ - 1));

    const float lf0    = log10f(fZs[0]);
    const float inv_lf = 1.0f / (log10f(fZs[1]) - lf0);

    int cur = -1;
    for (int e = 0; e < EPG; ++e) {
        const int t = g_order[grp * EPG + e];
        float find = (log10f(fZ_vals[t]) - lf0) * inv_lf;
        int f0 = (int)floorf(find) + 1;
        f0 = max(0, min(f0, NFZ - 2));

        __syncthreads();   // prev epoch: red reads + slab/ssv reads complete

        // stage copy (coalesced)
        {
            const float2* gf = g_f + (size_t)t * NORB;
            sf[tid]            = gf[tid];
            sf[tid + NTHREADS] = gf[tid + NTHREADS];
            const unsigned int* gs = (const unsigned int*)(g_s + (size_t)t * NORB);
            ssv[tid & 511] = gs[tid & 511];          // tid<512 always; mask keeps compiler calm
        }

        // fill slab only when fZ bin changes (epochs sorted by bin)
        if (f0 != cur) {
            cur = f0;
            const float* src = grid
                + ((size_t)(f0 * NKEZ + kez) * NTINT + h * HTINT) * NALPHA;
            #pragma unroll 4
            for (int idx = tid; idx < HTINT * NALPHA; idx += NTHREADS) {
                int a = idx >> 4;
                int j = idx & 15;
                float g0 = src[j * NALPHA + a];
                float g1 = src[j * NALPHA + min(a + 1, NALPHA - 1)];
                slab2[idx] = make_float2(g0, g1 - g0);   // coalesced STS.64
            }
        }
        __syncthreads();

        // main loop: warp w -> orbits [w*64, w*64+64), lane = (ohalf, tint)
        int c = 0;
        const int obeg = w * 64;
        const uint2*  ssv2 = (const uint2*)ssv;
        const float4* sf4  = (const float4*)sf;

        #pragma unroll 4
        for (int b = 0; b < 16; ++b) {
            const int o = obeg + b * 4;
            uint2 sv = ssv2[o >> 2];                 // s[o..o+3] broadcast
            unsigned int sel = ohalf ? sv.y : sv.x;  // this half's two orbits
            float4 f4 = sf4[(o >> 1) + ohalf];       // (dalA,dmA,dalB,dmB)

            float2 gA = slab2[(sel & 0xFFFFu) * 16 + tint];  // contiguous 128B/half
            float2 gB = slab2[(sel >> 16)     * 16 + tint];

            float dA = fmaf(f4.x, gA.y, gA.x);
            float dB = fmaf(f4.z, gB.y, gB.x);
            c += (f4.y < dA);
            c += (f4.w < dB);
        }
        c += __shfl_xor_sync(0xFFFFFFFFu, c, 16);    // fold orbit halves

        __syncthreads();                             // ssv reads done before alias write
        int* red = (int*)ssv;                        // red[16 warps][16 tints] aliases ssv
        if (ohalf == 0) red[w * HTINT + tint] = c;
        __syncthreads();

        if (tid < HTINT) {
            int csum = 0;
            #pragma unroll
            for (int ww = 0; ww < NWARPS; ++ww) csum += red[ww * HTINT + tid];
            out[t * NTINT + h * HTINT + tid] = (float)csum * (1.0f / NORB);
        }
    }
}

extern "C" void kernel_launch(void* const* d_in, const int* in_sizes, int n_in,
                              void* d_out, int out_size)
{
    (void)in_sizes; (void)n_in; (void)out_size;
    const float* alpha   = (const float*)d_in[0];
    const float* dMag    = (const float*)d_in[1];
    const float* fZ_vals = (const float*)d_in[2];
    const float* kEZ_val = (const float*)d_in[3];
    const float* grid    = (const float*)d_in[4];
    const float* fZs     = (const float*)d_in[5];
    const float* kEZs    = (const float*)d_in[6];
    const float* alphas  = (const float*)d_in[7];
    float* out = (float*)d_out;

    dim3 sgrid(NTIMES / 32, NORB / 32);
    stage_kernel<<<sgrid, dim3(32, 32)>>>(alpha, dMag, alphas);
    bin_kernel<<<1, NTIMES>>>(fZ_vals, fZs);

    cudaFuncSetAttribute(pdet_kernel,
                         cudaFuncAttributeMaxDynamicSharedMemorySize, SMEM_BYTES);
    dim3 mgrid(NTIMES / EPG, NTINT / HTINT);
    pdet_kernel<<<mgrid, NTHREADS, SMEM_BYTES>>>(fZ_vals, kEZ_val, grid,
                                                 fZs, kEZs, out);
}

// round 6
// speedup vs baseline: 1.4080x; 1.4080x over previous
#include <cuda_runtime.h>
#include <math_constants.h>

#define NORB   1024
#define NTIMES 1024
#define NFZ    24
#define NKEZ   6
#define NTINT  64
#define NALPHA 512

#define HTINT  16                       // tints per CTA (quarter)
#define RSP    513                      // pair-slab row stride in float2 (odd -> cf banks)

#define NTHREADS 512
#define NWARPS   16
#define ORB_PER_WARP (NORB / NWARPS)    // 64

// smem floats: slab2 [16][513] float2 = 16416f | sf [1024] float2 = 2048f | ssv 512f
#define SF_OFF   (HTINT * RSP * 2)      // 16416
#define SS_OFF   (SF_OFF + NORB * 2)    // +2048
#define SMEM_BYTES ((SS_OFF + 512) * 4) // 75904 B -> 3 CTAs/SM (same as R4)

// device scratch: per (epoch, orbit)
__device__ float2         g_f[NTIMES * NORB];   // (dalpha, dMag_masked)
__device__ unsigned short g_s[NTIMES * NORB];   // s index

// ---------------- pre-kernel: per-(epoch,orbit) stage, transposed -----------
__global__ __launch_bounds__(1024)
void stage_kernel(const float* __restrict__ alpha,
                  const float* __restrict__ dMag,
                  const float* __restrict__ alphas)
{
    __shared__ float2         tf[32][33];
    __shared__ unsigned short ts[32][33];
    const int tx = threadIdx.x, ty = threadIdx.y;
    const int t = blockIdx.x * 32 + tx;            // epoch (coalesced read dim)
    const int o = blockIdx.y * 32 + ty;            // orbit

    const float a_lo   = alphas[0];
    const float a_hi   = alphas[NALPHA - 1];
    const float la0    = __log10f(a_lo);
    const float inv_la = 1.0f / (__log10f(alphas[1]) - la0);

    float av = alpha[(size_t)o * NTIMES + t];
    float dm = dMag [(size_t)o * NTIMES + t];
    bool  m  = (av >= a_lo) && (av <= a_hi);
    float aind = (__log10f(av) - la0) * inv_la;
    int a0 = (int)aind;                            // trunc toward zero == astype(int32)
    a0 = max(0, min(a0, NALPHA - 1));
    float dal = aind - (float)a0;                  // dalpha vs clipped a0 (reference quirk)
    int s = min(a0, NALPHA - 2);                   // dynamic_slice clamp
    if (!m) dm = CUDART_INF_F;                     // geom_mask folded

    tf[ty][tx] = make_float2(dal, dm);
    ts[ty][tx] = (unsigned short)s;
    __syncthreads();

    const int tw = blockIdx.x * 32 + ty;
    const int ow = blockIdx.y * 32 + tx;
    g_f[(size_t)tw * NORB + ow] = tf[tx][ty];
    g_s[(size_t)tw * NORB + ow] = ts[tx][ty];
}

// ---------------- main kernel: one CTA = (epoch, tint-quarter) --------------
__global__ __launch_bounds__(NTHREADS, 3)
void pdet_kernel(const float* __restrict__ fZ_vals,
                 const float* __restrict__ kEZ_val,
                 const float* __restrict__ grid,
                 const float* __restrict__ fZs,
                 const float* __restrict__ kEZs,
                 float* __restrict__ out)
{
    extern __shared__ float sm[];
    float2*       slab2 = (float2*)sm;                  // [HTINT][RSP] (g0, g1-g0)
    float2*       sf    = (float2*)(sm + SF_OFF);       // [NORB] (dal, dm)
    unsigned int* ssv   = (unsigned int*)(sm + SS_OFF); // [512] packed 2x u16

    const int t   = blockIdx.x;
    const int h   = blockIdx.y;                         // tint quarter
    const int tid = threadIdx.x;
    const int w     = tid >> 5;
    const int lane  = tid & 31;
    const int tint  = lane & 15;
    const int ohalf = lane >> 4;

    // ---- fZ bin + kEZ index ----
    const float lf0    = __log10f(fZs[0]);
    const float inv_lf = 1.0f / (__log10f(fZs[1]) - lf0);
    const float kv = kEZ_val[0];
    int kez = -1;
    #pragma unroll
    for (int i = 0; i < NKEZ; ++i) kez += (kEZs[i] <= kv) ? 1 : 0;
    kez = max(0, min(kez, NKEZ - 1));

    float find = (__log10f(fZ_vals[t]) - lf0) * inv_lf;
    int f0 = (int)floorf(find) + 1;
    f0 = max(0, min(f0, NFZ - 2));

    // ---- fill pair slab: slab2[j][a] = (g[j][a], g[j][a+1]-g[j][a]) ----
    // iteration k: j = k, a = tid  -> LDG fully coalesced, STS.64 2-phase floor
    const float* src = grid
        + ((size_t)(f0 * NKEZ + kez) * NTINT + h * HTINT) * NALPHA;
    #pragma unroll 4
    for (int k = 0; k < HTINT; ++k) {
        float g0 = src[k * NALPHA + tid];
        float g1 = src[k * NALPHA + tid + 1];   // in-bounds: never last grid block
        slab2[k * RSP + tid] = make_float2(g0, g1 - g0);
    }

    // ---- stage copy (coalesced) ----
    {
        const float2* gf = g_f + (size_t)t * NORB;
        sf[tid]            = gf[tid];
        sf[tid + NTHREADS] = gf[tid + NTHREADS];
        const unsigned int* gs = (const unsigned int*)(g_s + (size_t)t * NORB);
        ssv[tid] = gs[tid];                      // 512 u32 = 1024 u16
    }
    __syncthreads();

    // ---- main loop: warp w -> orbits [w*64, w*64+64) ----
    // lane = (ohalf, tint); half0 -> orbits o,o+1; half1 -> o+2,o+3
    const float2* row = slab2 + tint * RSP;      // uniform per lane
    const uint2*  ssv2 = (const uint2*)ssv;
    const float4* sf4  = (const float4*)sf;
    int c = 0;
    const int obeg = w * ORB_PER_WARP;

    #pragma unroll 4
    for (int b = 0; b < ORB_PER_WARP / 4; ++b) {
        const int o = obeg + b * 4;
        uint2 sv = ssv2[o >> 2];                 // s[o..o+3], uniform broadcast
        unsigned int sel = ohalf ? sv.y : sv.x;  // this half's two s values
        float4 f4 = sf4[(o >> 1) + ohalf];       // (dalA,dmA,dalB,dmB)

        float2 gA = row[sel & 0xFFFFu];          // cf: 16 lanes cover all 32 banks
        float2 gB = row[sel >> 16];

        float dA = fmaf(f4.x, gA.y, gA.x);
        float dB = fmaf(f4.z, gB.y, gB.x);
        c += (f4.y < dA);
        c += (f4.w < dB);
    }
    c += __shfl_xor_sync(0xFFFFFFFFu, c, 16);    // fold orbit halves

    __syncthreads();                             // all ssv/sf/slab reads done
    int* red = (int*)ssv;                        // red[16 warps][16 tints] aliases ssv
    if (ohalf == 0) red[w * HTINT + tint] = c;
    __syncthreads();

    if (tid < HTINT) {
        int csum = 0;
        #pragma unroll
        for (int ww = 0; ww < NWARPS; ++ww) csum += red[ww * HTINT + tid];
        out[t * NTINT + h * HTINT + tid] = (float)csum * (1.0f / NORB);
    }
}

extern "C" void kernel_launch(void* const* d_in, const int* in_sizes, int n_in,
                              void* d_out, int out_size)
{
    (void)in_sizes; (void)n_in; (void)out_size;
    const float* alpha   = (const float*)d_in[0];
    const float* dMag    = (const float*)d_in[1];
    const float* fZ_vals = (const float*)d_in[2];
    const float* kEZ_val = (const float*)d_in[3];
    const float* grid    = (const float*)d_in[4];
    const float* fZs     = (const float*)d_in[5];
    const float* kEZs    = (const float*)d_in[6];
    const float* alphas  = (const float*)d_in[7];
    float* out = (float*)d_out;

    dim3 sgrid(NTIMES / 32, NORB / 32);
    stage_kernel<<<sgrid, dim3(32, 32)>>>(alpha, dMag, alphas);

    cudaFuncSetAttribute(pdet_kernel,
                         cudaFuncAttributeMaxDynamicSharedMemorySize, SMEM_BYTES);
    dim3 mgrid(NTIMES, NTINT / HTINT);
    pdet_kernel<<<mgrid, NTHREADS, SMEM_BYTES>>>(fZ_vals, kEZ_val, grid,
                                                 fZs, kEZs, out);
}

// round 7
// speedup vs baseline: 1.7055x; 1.2113x over previous
#include <cuda_runtime.h>
#include <math_constants.h>

#define NORB   1024
#define NTIMES 1024
#define NFZ    24
#define NKEZ   6
#define NTINT  64
#define NALPHA 512

#define HTINT  32                       // tints per CTA (half)
#define RS     513                      // slab row stride (odd -> conflict-free)

#define NTHREADS 512
#define NWARPS   16
#define ORB_PER_WARP (NORB / NWARPS)    // 64

#define SLAB_FLOATS  (HTINT * RS)       // 16416
#define SPK_OFF      SLAB_FLOATS        // float2 packed stage, 16B aligned (16416*4 % 16 == 0)
#define SMEM_BYTES   ((SPK_OFF + NORB * 2) * 4)   // 73856 B -> 3 CTAs/SM

// device scratch: per (epoch, orbit): {dMag_masked, (dal_23<<9)|s}
__device__ float2 g_pk[NTIMES * NORB];

// ---------------- pre-kernel: packed stage, transposed ----------------------
__global__ __launch_bounds__(1024)
void stage_kernel(const float* __restrict__ alpha,
                  const float* __restrict__ dMag,
                  const float* __restrict__ alphas)
{
    __shared__ float2 tile[32][33];
    const int tx = threadIdx.x, ty = threadIdx.y;
    const int t = blockIdx.x * 32 + tx;            // epoch (coalesced read dim)
    const int o = blockIdx.y * 32 + ty;            // orbit

    const float a_lo   = alphas[0];
    const float a_hi   = alphas[NALPHA - 1];
    // alpha index path is CONTINUOUS in aind -> fast log safe (unlike fZ bin).
    const float L10    = 0.434294481903251827651f; // 1/ln(10)
    const float la0    = log10f(a_lo);
    const float inv_la = 1.0f / (log10f(alphas[1]) - la0);

    float av = alpha[(size_t)o * NTIMES + t];
    float dm = dMag [(size_t)o * NTIMES + t];
    bool  m  = (av >= a_lo) && (av <= a_hi);
    float aind = (__logf(av) * L10 - la0) * inv_la;
    int a0 = (int)aind;                            // trunc toward zero == astype(int32)
    a0 = max(0, min(a0, NALPHA - 1));
    float dal = aind - (float)a0;                  // dalpha vs clipped a0 (reference quirk)
    int s = min(a0, NALPHA - 2);                   // dynamic_slice clamp
    if (!m) dm = CUDART_INF_F;                     // geom_mask folded (masked dal irrelevant)

    // pack: clamp dal into [0, 1) then 23-bit fixed point; s in low 9 bits
    float dc = fminf(fmaxf(dal, 0.0f), 0.99999988f);
    unsigned dal_m = (unsigned)(dc * 8388608.0f);  // 2^23
    unsigned pk = (dal_m << 9) | (unsigned)s;

    tile[ty][tx] = make_float2(dm, __uint_as_float(pk));
    __syncthreads();

    const int tw = blockIdx.x * 32 + ty;
    const int ow = blockIdx.y * 32 + tx;
    g_pk[(size_t)tw * NORB + ow] = tile[tx][ty];
}

// ---------------- main kernel: one CTA = (epoch, tint-half) -----------------
__global__ __launch_bounds__(NTHREADS, 3)
void pdet_kernel(const float* __restrict__ fZ_vals,
                 const float* __restrict__ kEZ_val,
                 const float* __restrict__ grid,
                 const float* __restrict__ fZs,
                 const float* __restrict__ kEZs,
                 float* __restrict__ out)
{
    extern __shared__ float sm[];
    float*  slab = sm;                             // [HTINT][RS]
    float2* spk  = (float2*)(sm + SPK_OFF);        // [NORB] {dm, packed}

    const int t   = blockIdx.x;
    const int h   = blockIdx.y;                    // tint half
    const int tid = threadIdx.x;
    const int w    = tid >> 5;
    const int lane = tid & 31;

    // ---- fZ bin (ACCURATE log10f: bin is discontinuous) + kEZ index ----
    const float lf0    = log10f(fZs[0]);
    const float inv_lf = 1.0f / (log10f(fZs[1]) - lf0);
    const float kv = kEZ_val[0];
    int kez = -1;
    #pragma unroll
    for (int i = 0; i < NKEZ; ++i) kez += (kEZs[i] <= kv) ? 1 : 0;
    kez = max(0, min(kez, NKEZ - 1));

    float find = (log10f(fZ_vals[t]) - lf0) * inv_lf;
    int f0 = (int)floorf(find) + 1;
    f0 = max(0, min(f0, NFZ - 2));

    // ---- fill slab: slab[j*RS + a] = grid[f0, kez, h*32+j, a] ----
    // k-iter: j=k, a=tid -> LDG fully coalesced, STS.32 conflict-free
    const float* src = grid
        + ((size_t)(f0 * NKEZ + kez) * NTINT + h * HTINT) * NALPHA;
    #pragma unroll 4
    for (int k = 0; k < HTINT; ++k)
        slab[k * RS + tid] = src[k * NALPHA + tid];

    // ---- stage copy (coalesced float2) ----
    {
        const float2* gp = g_pk + (size_t)t * NORB;
        spk[tid]            = gp[tid];
        spk[tid + NTHREADS] = gp[tid + NTHREADS];
    }
    __syncthreads();

    // ---- main loop: warp w -> 64 orbits, lane -> one tint ----
    const float* base = slab + lane * RS;          // banks (lane+s)%32: conflict-free
    const float4* spk4 = (const float4*)spk;
    int c = 0;
    const int obeg = w * ORB_PER_WARP;

    #pragma unroll 2
    for (int b = 0; b < ORB_PER_WARP / 4; ++b) {
        const int o = obeg + b * 4;
        float4 q0 = spk4[(o >> 1) + 0];            // {dm0,pk0,dm1,pk1} uniform bcast
        float4 q1 = spk4[(o >> 1) + 1];            // {dm2,pk2,dm3,pk3}

        unsigned u0 = __float_as_uint(q0.y);
        unsigned u1 = __float_as_uint(q0.w);
        unsigned u2 = __float_as_uint(q1.y);
        unsigned u3 = __float_as_uint(q1.w);

        const float* p0 = base + (u0 & 511u);
        const float* p1 = base + (u1 & 511u);
        const float* p2 = base + (u2 & 511u);
        const float* p3 = base + (u3 & 511u);

        float dal0 = __uint_as_float((u0 >> 9) | 0x3F800000u) - 1.0f;
        float dal1 = __uint_as_float((u1 >> 9) | 0x3F800000u) - 1.0f;
        float dal2 = __uint_as_float((u2 >> 9) | 0x3F800000u) - 1.0f;
        float dal3 = __uint_as_float((u3 >> 9) | 0x3F800000u) - 1.0f;

        float g00 = p0[0], g01 = p0[1];
        float g10 = p1[0], g11 = p1[1];
        float g20 = p2[0], g21 = p2[1];
        float g30 = p3[0], g31 = p3[1];

        float d;
        d = fmaf(dal0, g01 - g00, g00); c += (q0.x < d);
        d = fmaf(dal1, g11 - g10, g10); c += (q0.z < d);
        d = fmaf(dal2, g21 - g20, g20); c += (q1.x < d);
        d = fmaf(dal3, g31 - g30, g30); c += (q1.z < d);
    }

    // ---- reduce: red aliases spk after all reads complete ----
    __syncthreads();
    int* red = (int*)spk;                          // [NWARPS][HTINT]
    red[w * HTINT + lane] = c;
    __syncthreads();

    if (tid < HTINT) {
        int csum = 0;
        #pragma unroll
        for (int ww = 0; ww < NWARPS; ++ww) csum += red[ww * HTINT + tid];
        out[t * NTINT + h * HTINT + tid] = (float)csum * (1.0f / NORB);
    }
}

extern "C" void kernel_launch(void* const* d_in, const int* in_sizes, int n_in,
                              void* d_out, int out_size)
{
    (void)in_sizes; (void)n_in; (void)out_size;
    const float* alpha   = (const float*)d_in[0];
    const float* dMag    = (const float*)d_in[1];
    const float* fZ_vals = (const float*)d_in[2];
    const float* kEZ_val = (const float*)d_in[3];
    const float* grid    = (const float*)d_in[4];
    const float* fZs     = (const float*)d_in[5];
    const float* kEZs    = (const float*)d_in[6];
    const float* alphas  = (const float*)d_in[7];
    float* out = (float*)d_out;

    dim3 sgrid(NTIMES / 32, NORB / 32);
    stage_kernel<<<sgrid, dim3(32, 32)>>>(alpha, dMag, alphas);

    cudaFuncSetAttribute(pdet_kernel,
                         cudaFuncAttributeMaxDynamicSharedMemorySize, SMEM_BYTES);
    dim3 mgrid(NTIMES, NTINT / HTINT);
    pdet_kernel<<<mgrid, NTHREADS, SMEM_BYTES>>>(fZ_vals, kEZ_val, grid,
                                                 fZs, kEZs, out);
}

// round 10
// speedup vs baseline: 1.8760x; 1.0999x over previous
#include <cuda_runtime.h>
#include <math_constants.h>

#define NORB   1024
#define NTIMES 1024
#define NFZ    24
#define NKEZ   6
#define NTINT  64
#define NALPHA 512

#define HTINT  32                       // tints per CTA (half)
#define RS     34                       // slab row stride in floats (EVEN -> LDS.64 aligned)

#define NTHREADS 512
#define NWARPS   16
#define ORB_PER_WARP (NORB / NWARPS)    // 64

#define SLAB_FLOATS  (NALPHA * RS)      // 17408
#define SMEM_BYTES   (SLAB_FLOATS * 4)  // 69632 B -> 3 CTAs/SM (incl. 1KB/CTA reserve)

// device scratch: per (epoch, orbit): {dMag_masked, (dal_23<<9)|s}
__device__ float2 g_pk[NTIMES * NORB];

// ---------------- pre-kernel: packed stage, transposed ----------------------
__global__ __launch_bounds__(1024)
void stage_kernel(const float* __restrict__ alpha,
                  const float* __restrict__ dMag,
                  const float* __restrict__ alphas)
{
    __shared__ float2 tile[32][33];
    const int tx = threadIdx.x, ty = threadIdx.y;
    const int t = blockIdx.x * 32 + tx;            // epoch (coalesced read dim)
    const int o = blockIdx.y * 32 + ty;            // orbit

    const float a_lo   = alphas[0];
    const float a_hi   = alphas[NALPHA - 1];
    // alpha index path is CONTINUOUS in aind -> fast log safe (fZ bin is not).
    const float L10    = 0.434294481903251827651f; // 1/ln(10)
    const float la0    = log10f(a_lo);
    const float inv_la = 1.0f / (log10f(alphas[1]) - la0);

    float av = alpha[(size_t)o * NTIMES + t];
    float dm = dMag [(size_t)o * NTIMES + t];
    bool  m  = (av >= a_lo) && (av <= a_hi);
    float aind = (__logf(av) * L10 - la0) * inv_la;
    int a0 = (int)aind;                            // trunc toward zero == astype(int32)
    a0 = max(0, min(a0, NALPHA - 1));
    float dal = aind - (float)a0;                  // dalpha vs clipped a0 (reference quirk)
    int s = min(a0, NALPHA - 2);                   // dynamic_slice clamp
    if (!m) dm = CUDART_INF_F;                     // geom_mask folded

    float dc = fminf(fmaxf(dal, 0.0f), 0.99999988f);
    unsigned dal_m = (unsigned)(dc * 8388608.0f);  // 23-bit fixed point
    unsigned pk = (dal_m << 9) | (unsigned)s;

    tile[ty][tx] = make_float2(dm, __uint_as_float(pk));
    __syncthreads();

    const int tw = blockIdx.x * 32 + ty;
    const int ow = blockIdx.y * 32 + tx;
    g_pk[(size_t)tw * NORB + ow] = tile[tx][ty];
}

// ---------------- main kernel: one CTA = (epoch, tint-half) -----------------
__global__ __launch_bounds__(NTHREADS, 3)
void pdet_kernel(const float* __restrict__ fZ_vals,
                 const float* __restrict__ kEZ_val,
                 const float* __restrict__ grid,
                 const float* __restrict__ fZs,
                 const float* __restrict__ kEZs,
                 float* __restrict__ out)
{
    extern __shared__ float sm[];
    float* slab = sm;                              // [NALPHA][RS] alpha-major

    const int t   = blockIdx.x;
    const int h   = blockIdx.y;                    // tint half
    const int tid = threadIdx.x;
    const int w     = tid >> 5;
    const int lane  = tid & 31;
    const int k16   = lane & 15;                   // tint pair index (0..15)
    const int ohalf = lane >> 4;

    // ---- fZ bin (accurate log10f: discontinuous) + kEZ index ----
    const float lf0    = log10f(fZs[0]);
    const float inv_lf = 1.0f / (log10f(fZs[1]) - lf0);
    const float kv = kEZ_val[0];
    int kez = -1;
    #pragma unroll
    for (int i = 0; i < NKEZ; ++i) kez += (kEZs[i] <= kv) ? 1 : 0;
    kez = max(0, min(kez, NKEZ - 1));

    float find = (log10f(fZ_vals[t]) - lf0) * inv_lf;
    int f0 = (int)floorf(find) + 1;
    f0 = max(0, min(f0, NFZ - 2));

    // ---- fill slab transposed: slab[a*RS + j] = grid[f0, kez, h*32+j, a] ----
    // a = tid, j pair per iter: LDG coalesced; STS.64 bank-pairs (a+i)%16 cf.
    const float* src = grid
        + ((size_t)(f0 * NKEZ + kez) * NTINT + h * HTINT) * NALPHA;
    float2* slab2 = (float2*)slab;                 // float2 index = 17*a + i
    #pragma unroll 4
    for (int i = 0; i < HTINT / 2; ++i) {
        float e0 = src[(2 * i)     * NALPHA + tid];
        float e1 = src[(2 * i + 1) * NALPHA + tid];
        slab2[17 * tid + i] = make_float2(e0, e1);
    }
    __syncthreads();

    // ---- main loop: warp w -> 64 orbits; half-warps split orbits; lane -> 2 tints
    // stage comes from L2 via warp-uniform LDG.128 with distance-1 prefetch.
    const float* base = slab + 2 * k16;            // byte 8*k16, 8B aligned
    const float4* gq = (const float4*)(g_pk + (size_t)t * NORB)
                       + (size_t)(w * (ORB_PER_WARP / 2));  // this warp's 32 float4
    int c0 = 0, c1 = 0;

    float4 q = __ldg(gq + ohalf);                  // group 0 for this half
    #pragma unroll 4
    for (int b = 0; b < ORB_PER_WARP / 4; ++b) {
        int nb = (b < ORB_PER_WARP / 4 - 1) ? (b + 1) : b;
        float4 qn = __ldg(gq + nb * 2 + ohalf);    // prefetch next group

        unsigned uA = __float_as_uint(q.y);
        unsigned uB = __float_as_uint(q.w);

        const float* pA = base + (uA & 511u) * RS; // byte 136*s: 8B aligned
        const float* pB = base + (uB & 511u) * RS;

        float2 gA0 = *(const float2*)(pA);         // (tint, tint+1) at alpha s
        float2 gA1 = *(const float2*)(pA + RS);    // alpha s+1, imm offset +136B
        float2 gB0 = *(const float2*)(pB);
        float2 gB1 = *(const float2*)(pB + RS);

        float dalA = __uint_as_float((uA >> 9) | 0x3F800000u) - 1.0f;
        float dalB = __uint_as_float((uB >> 9) | 0x3F800000u) - 1.0f;

        float d;
        d = fmaf(dalA, gA1.x - gA0.x, gA0.x); c0 += (q.x < d);
        d = fmaf(dalA, gA1.y - gA0.y, gA0.y); c1 += (q.x < d);
        d = fmaf(dalB, gB1.x - gB0.x, gB0.x); c0 += (q.z < d);
        d = fmaf(dalB, gB1.y - gB0.y, gB0.y); c1 += (q.z < d);

        q = qn;
    }
    // fold orbit halves
    c0 += __shfl_xor_sync(0xFFFFFFFFu, c0, 16);
    c1 += __shfl_xor_sync(0xFFFFFFFFu, c1, 16);

    // ---- reduce: red aliases slab after all reads complete ----
    __syncthreads();
    int* red = (int*)slab;                         // [NWARPS][HTINT]
    if (ohalf == 0) {
        red[w * HTINT + 2 * k16]     = c0;
        red[w * HTINT + 2 * k16 + 1] = c1;
    }
    __syncthreads();

    if (tid < HTINT) {
        int csum = 0;
        #pragma unroll
        for (int ww = 0; ww < NWARPS; ++ww) csum += red[ww * HTINT + tid];
        out[t * NTINT + h * HTINT + tid] = (float)csum * (1.0f / NORB);
    }
}

extern "C" void kernel_launch(void* const* d_in, const int* in_sizes, int n_in,
                              void* d_out, int out_size)
{
    (void)in_sizes; (void)n_in; (void)out_size;
    const float* alpha   = (const float*)d_in[0];
    const float* dMag    = (const float*)d_in[1];
    const float* fZ_vals = (const float*)d_in[2];
    const float* kEZ_val = (const float*)d_in[3];
    const float* grid    = (const float*)d_in[4];
    const float* fZs     = (const float*)d_in[5];
    const float* kEZs    = (const float*)d_in[6];
    const float* alphas  = (const float*)d_in[7];
    float* out = (float*)d_out;

    dim3 sgrid(NTIMES / 32, NORB / 32);
    stage_kernel<<<sgrid, dim3(32, 32)>>>(alpha, dMag, alphas);

    cudaFuncSetAttribute(pdet_kernel,
                         cudaFuncAttributeMaxDynamicSharedMemorySize, SMEM_BYTES);
    dim3 mgrid(NTIMES, NTINT / HTINT);
    pdet_kernel<<<mgrid, NTHREADS, SMEM_BYTES>>>(fZ_vals, kEZ_val, grid,
                                                 fZs, kEZs, out);
}

// round 11
// speedup vs baseline: 2.0567x; 1.0963x over previous
#include <cuda_runtime.h>
#include <math_constants.h>

#define NORB   1024
#define NTIMES 1024
#define NFZ    24
#define NKEZ   6
#define NTINT  64
#define NALPHA 512

#define HTINT  32                       // tints per CTA (half)
#define RS     36                       // slab row stride in floats (144B, 16B-aligned quads)

#define NTHREADS 512
#define NWARPS   16
#define ORB_PER_WARP (NORB / NWARPS)    // 64

#define SLAB_FLOATS  (NALPHA * RS)      // 18432
#define SMEM_BYTES   (SLAB_FLOATS * 4)  // 73728 B -> 3 CTAs/SM

// device scratch: per (epoch, orbit): {dMag_masked, (dal_23<<9)|s}
__device__ float2 g_pk[NTIMES * NORB];

// ---------------- pre-kernel: packed stage, transposed ----------------------
__global__ __launch_bounds__(1024)
void stage_kernel(const float* __restrict__ alpha,
                  const float* __restrict__ dMag,
                  const float* __restrict__ alphas)
{
    __shared__ float2 tile[32][33];
    const int tx = threadIdx.x, ty = threadIdx.y;
    const int t = blockIdx.x * 32 + tx;            // epoch (coalesced read dim)
    const int o = blockIdx.y * 32 + ty;            // orbit

    const float a_lo   = alphas[0];
    const float a_hi   = alphas[NALPHA - 1];
    // alpha index path is CONTINUOUS in aind -> fast log safe (fZ bin is not).
    const float L10    = 0.434294481903251827651f; // 1/ln(10)
    const float la0    = log10f(a_lo);
    const float inv_la = 1.0f / (log10f(alphas[1]) - la0);

    float av = alpha[(size_t)o * NTIMES + t];
    float dm = dMag [(size_t)o * NTIMES + t];
    bool  m  = (av >= a_lo) && (av <= a_hi);
    float aind = (__logf(av) * L10 - la0) * inv_la;
    int a0 = (int)aind;                            // trunc toward zero == astype(int32)
    a0 = max(0, min(a0, NALPHA - 1));
    float dal = aind - (float)a0;                  // dalpha vs clipped a0 (reference quirk)
    int s = min(a0, NALPHA - 2);                   // dynamic_slice clamp
    if (!m) dm = CUDART_INF_F;                     // geom_mask folded

    float dc = fminf(fmaxf(dal, 0.0f), 0.99999988f);
    unsigned dal_m = (unsigned)(dc * 8388608.0f);  // 23-bit fixed point
    unsigned pk = (dal_m << 9) | (unsigned)s;

    tile[ty][tx] = make_float2(dm, __uint_as_float(pk));
    __syncthreads();

    const int tw = blockIdx.x * 32 + ty;
    const int ow = blockIdx.y * 32 + tx;
    g_pk[(size_t)tw * NORB + ow] = tile[tx][ty];
}

// ---------------- main kernel: one CTA = (epoch, tint-half) -----------------
__global__ __launch_bounds__(NTHREADS, 3)
void pdet_kernel(const float* __restrict__ fZ_vals,
                 const float* __restrict__ kEZ_val,
                 const float* __restrict__ grid,
                 const float* __restrict__ fZs,
                 const float* __restrict__ kEZs,
                 float* __restrict__ out)
{
    extern __shared__ float sm[];
    float* slab = sm;                              // [NALPHA][RS] alpha-major

    const int t   = blockIdx.x;
    const int h   = blockIdx.y;                    // tint half
    const int tid = threadIdx.x;
    const int w    = tid >> 5;
    const int lane = tid & 31;
    const int k4   = lane & 7;                     // tint quad index (0..7)
    const int qw   = lane >> 3;                    // orbit slot within group (0..3)

    // ---- fZ bin (accurate log10f: discontinuous) + kEZ index ----
    const float lf0    = log10f(fZs[0]);
    const float inv_lf = 1.0f / (log10f(fZs[1]) - lf0);
    const float kv = kEZ_val[0];
    int kez = -1;
    #pragma unroll
    for (int i = 0; i < NKEZ; ++i) kez += (kEZs[i] <= kv) ? 1 : 0;
    kez = max(0, min(kez, NKEZ - 1));

    float find = (log10f(fZ_vals[t]) - lf0) * inv_lf;
    int f0 = (int)floorf(find) + 1;
    f0 = max(0, min(f0, NFZ - 2));

    // ---- fill slab transposed: slab[a*RS + j] = grid[f0, kez, h*32+j, a] ----
    // a = tid: 4 coalesced LDGs per quad; STS.128 bank-quads 4(a+jq) distinct -> cf.
    const float* src = grid
        + ((size_t)(f0 * NKEZ + kez) * NTINT + h * HTINT) * NALPHA;
    #pragma unroll
    for (int jq = 0; jq < 8; ++jq) {
        float e0 = src[(4 * jq + 0) * NALPHA + tid];
        float e1 = src[(4 * jq + 1) * NALPHA + tid];
        float e2 = src[(4 * jq + 2) * NALPHA + tid];
        float e3 = src[(4 * jq + 3) * NALPHA + tid];
        *(float4*)(slab + tid * RS + 4 * jq) = make_float4(e0, e1, e2, e3);
    }

    // ---- wait for stage pre-kernel results (PDL: fill ran concurrently) ----
    cudaGridDependencySynchronize();
    __syncthreads();

    // ---- main loop: warp w -> 64 orbits; quarter-warp = 1 orbit x 8 lanes x 4 tints
    const float* base = slab + 4 * k4;             // this lane's tint quad
    const float2* gq = g_pk + (size_t)t * NORB + (size_t)(w * ORB_PER_WARP);
    int c0 = 0, c1 = 0, c2 = 0, c3 = 0;

    float2 q = __ldg(gq + qw);                     // group 0: this quarter's orbit
    #pragma unroll 4
    for (int b = 0; b < ORB_PER_WARP / 4; ++b) {
        int nb = (b < ORB_PER_WARP / 4 - 1) ? (b + 1) : b;
        float2 qn = __ldg(gq + nb * 4 + qw);       // prefetch next group

        unsigned u = __float_as_uint(q.y);
        const float4* p = (const float4*)(base + (u & 511u) * RS);

        float4 g0 = p[0];                          // 4 tints at alpha s (cf octets)
        float4 g1 = p[RS / 4];                     // alpha s+1 (+144B immediate)

        float dal = __uint_as_float((u >> 9) | 0x3F800000u) - 1.0f;
        float dmv = q.x;

        float d;
        d = fmaf(dal, g1.x - g0.x, g0.x); c0 += (dmv < d);
        d = fmaf(dal, g1.y - g0.y, g0.y); c1 += (dmv < d);
        d = fmaf(dal, g1.z - g0.z, g0.z); c2 += (dmv < d);
        d = fmaf(dal, g1.w - g0.w, g0.w); c3 += (dmv < d);

        q = qn;
    }
    // fold the 4 orbit quarter-warps (lanes differing in bits 3,4)
    c0 += __shfl_xor_sync(0xFFFFFFFFu, c0, 8);
    c1 += __shfl_xor_sync(0xFFFFFFFFu, c1, 8);
    c2 += __shfl_xor_sync(0xFFFFFFFFu, c2, 8);
    c3 += __shfl_xor_sync(0xFFFFFFFFu, c3, 8);
    c0 += __shfl_xor_sync(0xFFFFFFFFu, c0, 16);
    c1 += __shfl_xor_sync(0xFFFFFFFFu, c1, 16);
    c2 += __shfl_xor_sync(0xFFFFFFFFu, c2, 16);
    c3 += __shfl_xor_sync(0xFFFFFFFFu, c3, 16);

    // ---- reduce: red aliases slab after all reads complete ----
    __syncthreads();
    int4* red4 = (int4*)slab;                      // [NWARPS][8] int4 = [NWARPS][32] int
    if (lane < 8)
        red4[w * 8 + k4] = make_int4(c0, c1, c2, c3);
    __syncthreads();

    if (tid < HTINT) {
        const int* red = (const int*)slab;
        int csum = 0;
        #pragma unroll
        for (int ww = 0; ww < NWARPS; ++ww) csum += red[ww * HTINT + tid];
        out[t * NTINT + h * HTINT + tid] = (float)csum * (1.0f / NORB);
    }
}

extern "C" void kernel_launch(void* const* d_in, const int* in_sizes, int n_in,
                              void* d_out, int out_size)
{
    (void)in_sizes; (void)n_in; (void)out_size;
    const float* alpha   = (const float*)d_in[0];
    const float* dMag    = (const float*)d_in[1];
    const float* fZ_vals = (const float*)d_in[2];
    const float* kEZ_val = (const float*)d_in[3];
    const float* grid    = (const float*)d_in[4];
    const float* fZs     = (const float*)d_in[5];
    const float* kEZs    = (const float*)d_in[6];
    const float* alphas  = (const float*)d_in[7];
    float* out = (float*)d_out;

    dim3 sgrid(NTIMES / 32, NORB / 32);
    stage_kernel<<<sgrid, dim3(32, 32)>>>(alpha, dMag, alphas);

    cudaFuncSetAttribute(pdet_kernel,
                         cudaFuncAttributeMaxDynamicSharedMemorySize, SMEM_BYTES);

    // PDL: let pdet launch early and run its fill (grid-only) phase while
    // stage_kernel drains; cudaGridDependencySynchronize() gates g_pk reads.
    cudaLaunchConfig_t cfg = {};
    cfg.gridDim  = dim3(NTIMES, NTINT / HTINT);
    cfg.blockDim = dim3(NTHREADS, 1, 1);
    cfg.dynamicSmemBytes = SMEM_BYTES;
    cfg.stream = 0;
    cudaLaunchAttribute attr[1];
    attr[0].id = cudaLaunchAttributeProgrammaticStreamSerialization;
    attr[0].val.programmaticStreamSerializationAllowed = 1;
    cfg.attrs = attr;
    cfg.numAttrs = 1;
    cudaLaunchKernelEx(&cfg, pdet_kernel, fZ_vals, kEZ_val, grid, fZs, kEZs, out);
}